// round 3
// baseline (speedup 1.0000x reference)
#include <cuda_runtime.h>
#include <cuda_bf16.h>
#include <cstdint>

#define NU 100000          // users
#define NM 20000           // movies
#define NE 1000000         // edges per direction
#define NLOOP 20000        // self loops (min(NU,NM))
#define ET (NE + NLOOP)
#define HD 64

// ---------------- scratch (static device globals) ---------------------------
__device__ int   g_cntm[NM],  g_cntu[NU];
__device__ int   g_offm[NM+1], g_offu[NU+1];
__device__ int   g_curm[NM],  g_curu[NU];
__device__ int   g_csrm[ET],  g_csru[ET];
__device__ float g_xlu[(size_t)NU * HD];   // user  src-proj (xl of u2m)
__device__ float g_xru[(size_t)NU * HD];   // user  dst-proj (xr of m2u)
__device__ float g_xlm[(size_t)NM * HD];   // movie src-proj (xl of m2u)
__device__ float g_xrm[(size_t)NM * HD];   // movie dst-proj (xr of u2m)
__device__ float g_xu[(size_t)NU * HD];    // layer-0 user output
__device__ float g_xm[(size_t)NM * HD];    // layer-0 movie output

// ---------------- small utility kernels -------------------------------------
__global__ void zero_k(int* __restrict__ p, int n)
{
    int i = blockIdx.x * blockDim.x + threadIdx.x;
    if (i < n) p[i] = 0;
}

__global__ void hist_k(const int* __restrict__ edst, int* __restrict__ cnt)
{
    int e = blockIdx.x * blockDim.x + threadIdx.x;
    if (e >= ET) return;
    int d = (e < NE) ? edst[e] : e - NE;
    atomicAdd(&cnt[d], 1);
}

// single-block exclusive scan over n counts -> off[0..n], cursor copy
__global__ void scan_k(const int* __restrict__ cnt, int* __restrict__ off,
                       int* __restrict__ cur, int n)
{
    __shared__ int part[1024];
    int t = threadIdx.x;
    int chunk = (n + 1023) >> 10;
    int b = t * chunk;
    int e = min(b + chunk, n);
    int s = 0;
    for (int i = b; i < e; i++) s += cnt[i];
    part[t] = s;
    __syncthreads();
    for (int o = 1; o < 1024; o <<= 1) {
        int v = (t >= o) ? part[t - o] : 0;
        __syncthreads();
        part[t] += v;
        __syncthreads();
    }
    int run = (t == 0) ? 0 : part[t - 1];
    for (int i = b; i < e; i++) {
        off[i] = run; cur[i] = run;
        run += cnt[i];
    }
    if (t == 1023) off[n] = part[1023];
}

__global__ void reorder_k(const int* __restrict__ esrc, const int* __restrict__ edst,
                          int* __restrict__ cur, int* __restrict__ csr)
{
    int e = blockIdx.x * blockDim.x + threadIdx.x;
    if (e >= ET) return;
    int s, d;
    if (e < NE) { s = esrc[e]; d = edst[e]; } else { s = e - NE; d = s; }
    int pos = atomicAdd(&cur[d], 1);
    csr[pos] = s;
}

// ---------------- dual-output GEMM: Y1 = X@W1+B1, Y2 = X@W2+B2 ---------------
__global__ void gemm2_k(const float* __restrict__ X,
                        const float* __restrict__ W1, const float* __restrict__ B1,
                        const float* __restrict__ W2, const float* __restrict__ B2,
                        float* __restrict__ Y1, float* __restrict__ Y2, int N)
{
    __shared__ float Xs[64][65];
    __shared__ float Ws1[64][64];
    __shared__ float Ws2[64][64];
    int tid  = threadIdx.x;              // 256 threads
    int row0 = blockIdx.x * 64;

#pragma unroll
    for (int i = 0; i < 4; i++) {
        ((float4*)Ws1)[tid + i * 256] = ((const float4*)W1)[tid + i * 256];
        ((float4*)Ws2)[tid + i * 256] = ((const float4*)W2)[tid + i * 256];
    }
#pragma unroll
    for (int i = 0; i < 4; i++) {
        int idx = tid + i * 256;
        int r = idx >> 4, c4 = idx & 15;
        float4 v = make_float4(0.f, 0.f, 0.f, 0.f);
        if (row0 + r < N) v = ((const float4*)X)[(size_t)(row0 + r) * 16 + c4];
        Xs[r][c4 * 4 + 0] = v.x; Xs[r][c4 * 4 + 1] = v.y;
        Xs[r][c4 * 4 + 2] = v.z; Xs[r][c4 * 4 + 3] = v.w;
    }
    __syncthreads();

    int ty = tid >> 4, tx = tid & 15;
    float a1[4][4], a2[4][4];
#pragma unroll
    for (int i = 0; i < 4; i++)
#pragma unroll
        for (int j = 0; j < 4; j++) { a1[i][j] = 0.f; a2[i][j] = 0.f; }

#pragma unroll
    for (int k = 0; k < 64; k++) {
        float4 w1 = ((const float4*)Ws1)[k * 16 + tx];
        float4 w2 = ((const float4*)Ws2)[k * 16 + tx];
        float x0 = Xs[ty * 4 + 0][k];
        float x1 = Xs[ty * 4 + 1][k];
        float x2 = Xs[ty * 4 + 2][k];
        float x3 = Xs[ty * 4 + 3][k];
        a1[0][0] += x0*w1.x; a1[0][1] += x0*w1.y; a1[0][2] += x0*w1.z; a1[0][3] += x0*w1.w;
        a1[1][0] += x1*w1.x; a1[1][1] += x1*w1.y; a1[1][2] += x1*w1.z; a1[1][3] += x1*w1.w;
        a1[2][0] += x2*w1.x; a1[2][1] += x2*w1.y; a1[2][2] += x2*w1.z; a1[2][3] += x2*w1.w;
        a1[3][0] += x3*w1.x; a1[3][1] += x3*w1.y; a1[3][2] += x3*w1.z; a1[3][3] += x3*w1.w;
        a2[0][0] += x0*w2.x; a2[0][1] += x0*w2.y; a2[0][2] += x0*w2.z; a2[0][3] += x0*w2.w;
        a2[1][0] += x1*w2.x; a2[1][1] += x1*w2.y; a2[1][2] += x1*w2.z; a2[1][3] += x1*w2.w;
        a2[2][0] += x2*w2.x; a2[2][1] += x2*w2.y; a2[2][2] += x2*w2.z; a2[2][3] += x2*w2.w;
        a2[3][0] += x3*w2.x; a2[3][1] += x3*w2.y; a2[3][2] += x3*w2.z; a2[3][3] += x3*w2.w;
    }

    float4 b1 = ((const float4*)B1)[tx];
    float4 b2 = ((const float4*)B2)[tx];
#pragma unroll
    for (int i = 0; i < 4; i++) {
        int r = row0 + ty * 4 + i;
        if (r < N) {
            float4 o1, o2;
            o1.x = a1[i][0] + b1.x; o1.y = a1[i][1] + b1.y;
            o1.z = a1[i][2] + b1.z; o1.w = a1[i][3] + b1.w;
            o2.x = a2[i][0] + b2.x; o2.y = a2[i][1] + b2.y;
            o2.z = a2[i][2] + b2.z; o2.w = a2[i][3] + b2.w;
            ((float4*)Y1)[(size_t)r * 16 + tx] = o1;
            ((float4*)Y2)[(size_t)r * 16 + tx] = o2;
        }
    }
}

// ---------------- CSR conv: warp per dst, fully fused ------------------------
// out[d] = selu( (sum_e exp(score_e) * xl[src_e]) / (sum_e exp(score_e)) + bias )
__global__ void conv_csr_k(const int* __restrict__ off, const int* __restrict__ csr,
                           const float* __restrict__ xl, const float* __restrict__ xr,
                           const float* __restrict__ att, const float* __restrict__ bias,
                           float* __restrict__ out, int nd)
{
    int wid = (blockIdx.x * blockDim.x + threadIdx.x) >> 5;
    if (wid >= nd) return;
    int d = wid;
    int lane = threadIdx.x & 31;
    int half = lane >> 4;      // two edges in flight per iteration
    int l16  = lane & 15;      // 4 feature dims per lane

    int beg = off[d], end = off[d + 1];
    float4 xr4 = ((const float4*)xr)[(size_t)d * 16 + l16];
    float4 w4  = ((const float4*)att)[l16];

    float4 acc = make_float4(0.f, 0.f, 0.f, 0.f);
    float  sum = 0.f;

    int iters = (end - beg + 1) >> 1;
    for (int i = 0; i < iters; i++) {
        int e = beg + 2 * i + half;
        bool v = e < end;
        int src = csr[v ? e : beg];
        float4 a = ((const float4*)xl)[(size_t)src * 16 + l16];

        float vx = a.x + xr4.x; vx = vx > 0.f ? vx : 0.2f * vx;
        float vy = a.y + xr4.y; vy = vy > 0.f ? vy : 0.2f * vy;
        float vz = a.z + xr4.z; vz = vz > 0.f ? vz : 0.2f * vz;
        float vw = a.w + xr4.w; vw = vw > 0.f ? vw : 0.2f * vw;
        float p = vx * w4.x + vy * w4.y + vz * w4.z + vw * w4.w;
#pragma unroll
        for (int o = 8; o > 0; o >>= 1) p += __shfl_xor_sync(0xffffffffu, p, o);

        float ex = v ? __expf(p) : 0.f;
        sum   += ex;
        acc.x += ex * a.x; acc.y += ex * a.y;
        acc.z += ex * a.z; acc.w += ex * a.w;
    }

    // combine the two half-warps (same dims live at lane and lane^16)
    acc.x += __shfl_xor_sync(0xffffffffu, acc.x, 16);
    acc.y += __shfl_xor_sync(0xffffffffu, acc.y, 16);
    acc.z += __shfl_xor_sync(0xffffffffu, acc.z, 16);
    acc.w += __shfl_xor_sync(0xffffffffu, acc.w, 16);
    sum   += __shfl_xor_sync(0xffffffffu, sum,   16);

    if (half == 0) {
        float inv = 1.f / (sum + 1e-16f);
        float4 b4 = ((const float4*)bias)[l16];
        float4 o;
        o.x = acc.x * inv + b4.x; o.y = acc.y * inv + b4.y;
        o.z = acc.z * inv + b4.z; o.w = acc.w * inv + b4.w;
        const float SCALE = 1.0507009873554805f;
        const float SA    = 1.7580993408473766f;   // scale * alpha
        o.x = o.x > 0.f ? SCALE * o.x : SA * (__expf(o.x) - 1.f);
        o.y = o.y > 0.f ? SCALE * o.y : SA * (__expf(o.y) - 1.f);
        o.z = o.z > 0.f ? SCALE * o.z : SA * (__expf(o.z) - 1.f);
        o.w = o.w > 0.f ? SCALE * o.w : SA * (__expf(o.w) - 1.f);
        ((float4*)out)[(size_t)d * 16 + l16] = o;
    }
}

// ---------------- host ------------------------------------------------------
extern "C" void kernel_launch(void* const* d_in, const int* in_sizes, int n_in,
                              void* d_out, int out_size)
{
    const float* x_user  = (const float*)d_in[0];
    const float* x_movie = (const float*)d_in[1];
    const int*   e_u2m   = (const int*)d_in[2];
    const int*   e_m2u   = (const int*)d_in[3];
    const float* Wl      = (const float*)d_in[4];
    const float* bl      = (const float*)d_in[5];
    const float* Wr      = (const float*)d_in[6];
    const float* br      = (const float*)d_in[7];
    const float* att     = (const float*)d_in[8];
    const float* bias    = (const float*)d_in[9];
    float* out = (float*)d_out;

    int *cntm, *cntu, *offm, *offu, *curm, *curu, *csrm, *csru;
    float *xlu, *xru, *xlm, *xrm, *xu, *xm;
    cudaGetSymbolAddress((void**)&cntm, g_cntm);
    cudaGetSymbolAddress((void**)&cntu, g_cntu);
    cudaGetSymbolAddress((void**)&offm, g_offm);
    cudaGetSymbolAddress((void**)&offu, g_offu);
    cudaGetSymbolAddress((void**)&curm, g_curm);
    cudaGetSymbolAddress((void**)&curu, g_curu);
    cudaGetSymbolAddress((void**)&csrm, g_csrm);
    cudaGetSymbolAddress((void**)&csru, g_csru);
    cudaGetSymbolAddress((void**)&xlu,  g_xlu);
    cudaGetSymbolAddress((void**)&xru,  g_xru);
    cudaGetSymbolAddress((void**)&xlm,  g_xlm);
    cudaGetSymbolAddress((void**)&xrm,  g_xrm);
    cudaGetSymbolAddress((void**)&xu,   g_xu);
    cudaGetSymbolAddress((void**)&xm,   g_xm);

    const int EB = (ET + 255) / 256;

    // ---- build CSR (per dst) for both edge directions, reused by both layers
    zero_k<<<(NM + 255) / 256, 256>>>(cntm, NM);
    zero_k<<<(NU + 255) / 256, 256>>>(cntu, NU);
    hist_k<<<EB, 256>>>(e_u2m + NE, cntm);
    hist_k<<<EB, 256>>>(e_m2u + NE, cntu);
    scan_k<<<1, 1024>>>(cntm, offm, curm, NM);
    scan_k<<<1, 1024>>>(cntu, offu, curu, NU);
    reorder_k<<<EB, 256>>>(e_u2m, e_u2m + NE, curm, csrm);
    reorder_k<<<EB, 256>>>(e_m2u, e_m2u + NE, curu, csru);

    const float* cu = x_user;
    const float* cm = x_movie;

    for (int l = 0; l < 2; l++) {
        int p0 = l * 2 + 0;   // user -> movie
        int p1 = l * 2 + 1;   // movie -> user

        // projections: user feeds xl(u2m) and xr(m2u); movie feeds xl(m2u) and xr(u2m)
        gemm2_k<<<(NU + 63) / 64, 256>>>(cu,
            Wl + (size_t)p0 * 4096, bl + (size_t)p0 * 64,
            Wr + (size_t)p1 * 4096, br + (size_t)p1 * 64, xlu, xru, NU);
        gemm2_k<<<(NM + 63) / 64, 256>>>(cm,
            Wl + (size_t)p1 * 4096, bl + (size_t)p1 * 64,
            Wr + (size_t)p0 * 4096, br + (size_t)p0 * 64, xlm, xrm, NM);

        float* om = (l == 1) ? (out + (size_t)NU * HD) : xm;
        float* ou = (l == 1) ? out : xu;

        // u2m conv: dst = movies
        conv_csr_k<<<(NM * 32 + 255) / 256, 256>>>(offm, csrm, xlu, xrm,
            att + (size_t)p0 * 64, bias + (size_t)p0 * 64, om, NM);
        // m2u conv: dst = users
        conv_csr_k<<<(NU * 32 + 255) / 256, 256>>>(offu, csru, xlm, xru,
            att + (size_t)p1 * 64, bias + (size_t)p1 * 64, ou, NU);

        cu = xu;
        cm = xm;
    }
}